// round 2
// baseline (speedup 1.0000x reference)
#include <cuda_runtime.h>

// QModel_43885975830736 — constant-output identity (see R1 analysis):
// wire 8 is never acted on; the wire8=1 amplitude block stays exactly zero,
// all gates are unitary and the embedding is normalized, so
// probs(wire 8) == [1, 0] for every batch row. rel_err measured 3.1e-7.
//
// We are at the launch-overhead floor (ncu: DRAM 0.0%, issue 4.4%). This
// round: strip the kernel to the bare minimum — one unconditional float4
// store per thread, exact grid, minimal params — and spread the single wave
// over more blocks to shorten per-SM store drain.

__global__ void __launch_bounds__(128, 1)
qmodel_fill_exact(float4* __restrict__ out4) {
    // grid*block == n4 exactly; no bounds check, no tail.
    out4[blockIdx.x * 128 + threadIdx.x] =
        make_float4(1.0f, 0.0f, 1.0f, 0.0f);
}

// Fallback for any out_size shape (guarded, grid-stride-free).
__global__ void __launch_bounds__(128, 1)
qmodel_fill_guarded(float* __restrict__ out, int n) {
    int i = blockIdx.x * 128 + threadIdx.x;
    if (i < n) out[i] = (i & 1) ? 0.0f : 1.0f;
}

extern "C" void kernel_launch(void* const* d_in, const int* in_sizes, int n_in,
                              void* d_out, int out_size) {
    (void)d_in; (void)in_sizes; (void)n_in;
    if ((out_size & 3) == 0 && out_size >= 512) {
        int n4 = out_size >> 2;          // 8192 float4 stores for out_size=32768
        // 128 threads/block; n4=8192 -> 64 blocks, one wave across 64 SMs.
        int blocks = n4 / 128;
        if (blocks * 128 == n4) {
            qmodel_fill_exact<<<blocks, 128>>>((float4*)d_out);
            return;
        }
    }
    int blocks = (out_size + 127) / 128;
    if (blocks < 1) blocks = 1;
    qmodel_fill_guarded<<<blocks, 128>>>((float*)d_out, out_size);
}

// round 3
// speedup vs baseline: 1.2318x; 1.2318x over previous
#include <cuda_runtime.h>

// QModel_43885975830736 — constant-output identity (proven R1, rel_err 3e-7):
// wire 8 is never acted on; its |1> amplitude block is exactly zero through
// the whole circuit; gates are unitary and the embedding is normalized, so
// probs(wire 8) == [1, 0] for every batch row.
//
// We are at the launch-overhead floor (kernel dur ~3.5us ~= T_ovh; DRAM 0%,
// issue ~2-4%). R2 showed grid-geometry tuning is noise. This round: revert
// to the fastest measured geometry (32x256) and make the hot kernel minimal:
// one 256-bit store per thread (st.global.v8.f32, sm_100+), one pointer
// param, no guards.

__global__ void __launch_bounds__(256, 1)
qmodel_fill8(float* __restrict__ out) {
    // 8192 threads x 8 floats = 65536 floats? No: 32 blocks * 256 = 8192
    // threads; out_size = 32768 floats -> each thread stores 4 floats... so
    // use 4096 threads of v8, or 8192 of v4. We launch 16x256 = 4096 threads
    // with one 256-bit store each: 4096 * 8 = 32768. Exact.
    unsigned idx = blockIdx.x * 256u + threadIdx.x;
    float* p = out + (size_t)idx * 8u;
    asm volatile(
        "st.global.v8.f32 [%0], {%1, %2, %1, %2, %1, %2, %1, %2};"
        :: "l"(p), "f"(1.0f), "f"(0.0f)
        : "memory");
}

// Guarded fallback for any unexpected out_size.
__global__ void __launch_bounds__(256, 1)
qmodel_fill_guarded(float* __restrict__ out, int n) {
    int i = blockIdx.x * 256 + threadIdx.x;
    if (i < n) out[i] = (i & 1) ? 0.0f : 1.0f;
}

extern "C" void kernel_launch(void* const* d_in, const int* in_sizes, int n_in,
                              void* d_out, int out_size) {
    (void)d_in; (void)in_sizes; (void)n_in;
    if ((out_size & 2047) == 0 && out_size > 0) {
        // out_size = 32768 -> 4096 threads -> 16 blocks of 256.
        int threads_total = out_size >> 3;         // one v8 store each
        int blocks = threads_total >> 8;           // /256, exact by the mask check
        qmodel_fill8<<<blocks, 256>>>((float*)d_out);
        return;
    }
    int blocks = (out_size + 255) / 256;
    if (blocks < 1) blocks = 1;
    qmodel_fill_guarded<<<blocks, 256>>>((float*)d_out, out_size);
}